// round 2
// baseline (speedup 1.0000x reference)
#include <cuda_runtime.h>

// Problem constants
#define B_      16
#define CIN     320
#define COUT    320
#define H_      64
#define W_      64
#define RANK    4
#define NLORA   50
#define LSTRIDE 4
#define SCALE_  1.0f

// Tiling
#define TILE      16    // 16x16 spatial tile per CTA
#define CO_TILE   64    // couts per CTA
#define CBLK      8     // cin chunk
#define XS_STRIDE 21    // padded xs row stride (odd -> <=2-way LDS conflicts)
#define NTHREADS  256

__global__ __launch_bounds__(NTHREADS)
void lora_conv_kernel(const float* __restrict__ x,
                      const float* __restrict__ conv_w,
                      const float* __restrict__ conv_b,
                      const float* __restrict__ down_w,
                      const float* __restrict__ up_w,
                      const int* __restrict__ lora_id,   // int32! (JAX x64 disabled)
                      float* __restrict__ out)
{
    const int tid  = threadIdx.x;
    const int bidx = blockIdx.x;                 // 0..15 spatial tiles
    const int ob   = blockIdx.y * CO_TILE;       // cout base (5 groups)
    const int b    = blockIdx.z;                 // batch

    const int th0 = (bidx >> 2) * TILE;
    const int tw0 = (bidx & 3) * TILE;

    const int og   = tid >> 6;   // 0..3  cout subgroup (2 warps per og)
    const int pt   = tid & 63;   // 0..63 pixel-thread
    const int prow = pt >> 2;    // 0..15 row in tile
    const int pcg  = pt & 3;     // 0..3  col group (4 pixels each)

    const int lid = lora_id[b];
    const int idx = lid / LSTRIDE;               // lid >= 0 per generator
    const bool act = (idx >= 0);
    int safe = idx; if (safe < 0) safe = 0; if (safe > NLORA - 1) safe = NLORA - 1;

    __shared__ __align__(16) float xs[CBLK][18 * XS_STRIDE];
    __shared__ __align__(16) float ws[CBLK][9][CO_TILE];
    __shared__ __align__(16) float ds[CBLK][9][RANK];
    __shared__ __align__(16) float down_sh[4][RANK][TILE][TILE];

    float acc[16][4];
    #pragma unroll
    for (int i = 0; i < 16; i++)
        #pragma unroll
        for (int j = 0; j < 4; j++) acc[i][j] = 0.f;

    float dacc[RANK][4];
    #pragma unroll
    for (int r = 0; r < RANK; r++)
        #pragma unroll
        for (int j = 0; j < 4; j++) dacc[r][j] = 0.f;

    const float* wg = conv_w + (size_t)ob * (CIN * 9);
    const float* dg = down_w + (size_t)safe * (RANK * CIN * 9);
    const float* xg = x + (size_t)b * (CIN * H_ * W_);

    for (int c0 = 0; c0 < CIN; c0 += CBLK) {
        __syncthreads();  // protect smem from previous iteration's readers

        // ---- load x tile with halo: CBLK x 18 x 18 ----
        #pragma unroll 1
        for (int i = tid; i < CBLK * 18 * 18; i += NTHREADS) {
            int c  = i / 324;
            int rr = i - c * 324;
            int r  = rr / 18;
            int cl = rr - r * 18;
            int gh = th0 - 1 + r;
            int gw = tw0 - 1 + cl;
            float v = 0.f;
            if ((unsigned)gh < (unsigned)H_ && (unsigned)gw < (unsigned)W_)
                v = xg[(size_t)(c0 + c) * (H_ * W_) + gh * W_ + gw];
            xs[c][r * XS_STRIDE + cl] = v;
        }

        // ---- load base conv weights: CO_TILE x CBLK x 9 ----
        #pragma unroll 1
        for (int i = tid; i < CO_TILE * CBLK * 9; i += NTHREADS) {
            int o   = i / (CBLK * 9);
            int rem = i - o * (CBLK * 9);
            int c   = rem / 9;
            int tap = rem - c * 9;
            ws[c][tap][o] = wg[(size_t)o * (CIN * 9) + (c0 + c) * 9 + tap];
        }

        // ---- load LoRA down weights: RANK x CBLK x 9 ----
        #pragma unroll 1
        for (int i = tid; i < RANK * CBLK * 9; i += NTHREADS) {
            int r   = i / (CBLK * 9);
            int rem = i - r * (CBLK * 9);
            int c   = rem / 9;
            int tap = rem - c * 9;
            ds[c][tap][r] = dg[((size_t)r * CIN + (c0 + c)) * 9 + tap];
        }

        __syncthreads();

        const bool do_down = (((c0 / CBLK) & 3) == og);   // distribute down-conv chunks

        #pragma unroll
        for (int c = 0; c < CBLK; c++) {
            #pragma unroll
            for (int ky = 0; ky < 3; ky++) {
                // x row fragment for this thread's 4 pixels: cols pcg*4 .. pcg*4+5
                float xr[6];
                const float* xrow = &xs[c][(prow + ky) * XS_STRIDE + pcg * 4];
                #pragma unroll
                for (int i = 0; i < 6; i++) xr[i] = xrow[i];

                #pragma unroll
                for (int kx = 0; kx < 3; kx++) {
                    const int tap = ky * 3 + kx;
                    #pragma unroll
                    for (int oo = 0; oo < 16; oo += 4) {
                        const float4 w4 = *(const float4*)&ws[c][tap][og * 16 + oo];
                        #pragma unroll
                        for (int j = 0; j < 4; j++) {
                            const float xv = xr[kx + j];
                            acc[oo + 0][j] += w4.x * xv;
                            acc[oo + 1][j] += w4.y * xv;
                            acc[oo + 2][j] += w4.z * xv;
                            acc[oo + 3][j] += w4.w * xv;
                        }
                    }
                    if (do_down) {
                        const float4 d4 = *(const float4*)&ds[c][tap][0];
                        #pragma unroll
                        for (int j = 0; j < 4; j++) {
                            const float xv = xr[kx + j];
                            dacc[0][j] += d4.x * xv;
                            dacc[1][j] += d4.y * xv;
                            dacc[2][j] += d4.z * xv;
                            dacc[3][j] += d4.w * xv;
                        }
                    }
                }
            }
        }
    }

    // ---- reduce down partials across the 4 cout subgroups ----
    #pragma unroll
    for (int r = 0; r < RANK; r++)
        #pragma unroll
        for (int j = 0; j < 4; j++)
            down_sh[og][r][prow][pcg * 4 + j] = dacc[r][j];
    __syncthreads();

    float dsum[RANK][4];
    #pragma unroll
    for (int r = 0; r < RANK; r++)
        #pragma unroll
        for (int j = 0; j < 4; j++) {
            const int col = pcg * 4 + j;
            dsum[r][j] = down_sh[0][r][prow][col] + down_sh[1][r][prow][col]
                       + down_sh[2][r][prow][col] + down_sh[3][r][prow][col];
        }

    const float sact = act ? SCALE_ : 0.f;
    const int o0 = ob + og * 16;
    const size_t outbase = ((size_t)b * COUT + o0) * (H_ * W_)
                         + (size_t)(th0 + prow) * W_ + tw0 + pcg * 4;

    #pragma unroll
    for (int oo = 0; oo < 16; oo++) {
        const int o = o0 + oo;
        const float4 u4 = *(const float4*)&up_w[((size_t)safe * COUT + o) * RANK];
        const float bias = conv_b[o];
        float4 res;
        res.x = acc[oo][0] + bias + sact * (u4.x * dsum[0][0] + u4.y * dsum[1][0] + u4.z * dsum[2][0] + u4.w * dsum[3][0]);
        res.y = acc[oo][1] + bias + sact * (u4.x * dsum[0][1] + u4.y * dsum[1][1] + u4.z * dsum[2][1] + u4.w * dsum[3][1]);
        res.z = acc[oo][2] + bias + sact * (u4.x * dsum[0][2] + u4.y * dsum[1][2] + u4.z * dsum[2][2] + u4.w * dsum[3][2]);
        res.w = acc[oo][3] + bias + sact * (u4.x * dsum[0][3] + u4.y * dsum[1][3] + u4.z * dsum[2][3] + u4.w * dsum[3][3]);
        *(float4*)&out[outbase + (size_t)oo * (H_ * W_)] = res;
    }
}

extern "C" void kernel_launch(void* const* d_in, const int* in_sizes, int n_in,
                              void* d_out, int out_size)
{
    const float* x       = (const float*)d_in[0];
    const float* conv_w  = (const float*)d_in[1];
    const float* conv_b  = (const float*)d_in[2];
    const float* down_w  = (const float*)d_in[3];
    const float* up_w    = (const float*)d_in[4];
    const int*   lora_id = (const int*)d_in[5];   // int32 (JAX default, x64 off)
    float* out = (float*)d_out;

    dim3 grid((H_ / TILE) * (W_ / TILE),   // 16 spatial tiles
              COUT / CO_TILE,              // 5 cout groups
              B_);                         // 16 batches
    lora_conv_kernel<<<grid, NTHREADS>>>(x, conv_w, conv_b, down_w, up_w, lora_id, out);
}

// round 5
// speedup vs baseline: 5.1106x; 5.1106x over previous
#include <cuda_runtime.h>
#include <cuda_bf16.h>
#include <cstdint>

// ---------------- problem constants ----------------
#define B_      16
#define CIN     320
#define COUT    320
#define H_      64
#define W_      64
#define RANK    4
#define NLORA   50
#define KTOT    2880            // 9 taps * 320 cin
#define PAD_HW  66
#define PIX_PAD (PAD_HW * PAD_HW)

// ---------------- scratch ----------------
__device__ __align__(256) __nv_bfloat16 g_Xh[(size_t)B_ * PIX_PAD * CIN];
__device__ __align__(256) __nv_bfloat16 g_Xl[(size_t)B_ * PIX_PAD * CIN];
__device__ __align__(256) __nv_bfloat16 g_Wh[(size_t)COUT * KTOT];
__device__ __align__(256) __nv_bfloat16 g_Wl[(size_t)COUT * KTOT];
__device__ __align__(256) float        g_down[(size_t)B_ * 4096 * 4];

// ---------------- PTX helpers (base ISA only — compute_103 safe) ----------------
__device__ __forceinline__ uint32_t smem_u32(const void* p) {
    uint32_t a;
    asm("{ .reg .u64 t; cvta.to.shared.u64 t, %1; cvt.u32.u64 %0, t; }" : "=r"(a) : "l"(p));
    return a;
}
#define CP16(dst, src) asm volatile("cp.async.cg.shared.global [%0], [%1], 16;" :: "r"(dst), "l"(src))
#define CPCOMMIT()     asm volatile("cp.async.commit_group;" ::: "memory")
#define CPWAIT0()      asm volatile("cp.async.wait_group 0;" ::: "memory")
#define CPWAIT1()      asm volatile("cp.async.wait_group 1;" ::: "memory")

__device__ __forceinline__ void ldsm4(uint32_t& r0, uint32_t& r1, uint32_t& r2, uint32_t& r3, uint32_t a) {
    asm volatile("ldmatrix.sync.aligned.m8n8.x4.shared.b16 {%0,%1,%2,%3},[%4];"
                 : "=r"(r0), "=r"(r1), "=r"(r2), "=r"(r3) : "r"(a));
}
__device__ __forceinline__ void mma_bf16(float& c0, float& c1, float& c2, float& c3,
                                         uint32_t a0, uint32_t a1, uint32_t a2, uint32_t a3,
                                         uint32_t b0, uint32_t b1) {
    asm volatile("mma.sync.aligned.m16n8k16.row.col.f32.bf16.bf16.f32 "
                 "{%0,%1,%2,%3},{%4,%5,%6,%7},{%8,%9},{%0,%1,%2,%3};"
                 : "+f"(c0), "+f"(c1), "+f"(c2), "+f"(c3)
                 : "r"(a0), "r"(a1), "r"(a2), "r"(a3), "r"(b0), "r"(b1));
}

// ---------------- conversion kernels ----------------
// x[b, c, h, w] fp32 -> g_X{h,l}[b, (h+1)*66+(w+1), c] bf16 (hi/lo split)
__global__ void convx_kernel(const float* __restrict__ x) {
    extern __shared__ float s[];   // [CIN][65]
    const int h = blockIdx.x, b = blockIdx.y, tid = threadIdx.x;
    const float* src = x + ((size_t)b * CIN) * (H_ * W_) + h * W_;
    for (int i = tid; i < CIN * 64; i += 256) {
        int c = i >> 6, w = i & 63;
        s[c * 65 + w] = src[(size_t)c * (H_ * W_) + w];
    }
    __syncthreads();
    for (int i = tid; i < 64 * CIN; i += 256) {
        int w = i / CIN, c = i - w * CIN;
        float v = s[c * 65 + w];
        __nv_bfloat16 hi = __float2bfloat16(v);
        __nv_bfloat16 lo = __float2bfloat16(v - __bfloat162float(hi));
        size_t o = ((size_t)b * PIX_PAD + (size_t)(h + 1) * PAD_HW + (w + 1)) * CIN + c;
        g_Xh[o] = hi;
        g_Xl[o] = lo;
    }
}

__global__ void border_kernel() {
    const int total = B_ * 260 * CIN;
    const __nv_bfloat16 z = __float2bfloat16(0.f);
    for (int i = blockIdx.x * blockDim.x + threadIdx.x; i < total; i += gridDim.x * blockDim.x) {
        int c = i % CIN, t = i / CIN;
        int bi = t % 260, b = t / 260;
        int pp;
        if (bi < 66)       pp = bi;
        else if (bi < 132) pp = 65 * PAD_HW + (bi - 66);
        else if (bi < 196) pp = (bi - 131) * PAD_HW;
        else               pp = (bi - 195) * PAD_HW + 65;
        size_t o = ((size_t)b * PIX_PAD + pp) * CIN + c;
        g_Xh[o] = z;
        g_Xl[o] = z;
    }
}

// conv_w[n, c, tap] -> g_W{h,l}[n, tap*320 + c]
__global__ void convw_kernel(const float* __restrict__ conv_w) {
    const int NW = COUT * CIN;
    for (int i = blockIdx.x * blockDim.x + threadIdx.x; i < NW; i += gridDim.x * blockDim.x) {
        int n = i / CIN, c = i - n * CIN;
        #pragma unroll
        for (int tap = 0; tap < 9; tap++) {
            float v = conv_w[((size_t)n * CIN + c) * 9 + tap];
            __nv_bfloat16 hi = __float2bfloat16(v);
            __nv_bfloat16 lo = __float2bfloat16(v - __bfloat162float(hi));
            size_t o = (size_t)n * KTOT + tap * CIN + c;
            g_Wh[o] = hi;
            g_Wl[o] = lo;
        }
    }
}

// ---------------- LoRA down conv (rank 4, fp32 FFMA) ----------------
__global__ __launch_bounds__(256)
void down_kernel(const float* __restrict__ x, const float* __restrict__ down_w,
                 const int* __restrict__ lora_id) {
    __shared__ float xs[16][6 * PAD_HW];
    __shared__ float ds[16][36];

    const int tid = threadIdx.x;
    const int mtile = blockIdx.x;          // 0..15 (4 h-rows each)
    const int b = blockIdx.y;
    const int h0 = mtile * 4;
    const int hr = tid >> 6;
    const int w  = tid & 63;

    const int idx = lora_id[b] / 4;
    int safe = idx; if (safe < 0) safe = 0; if (safe > NLORA - 1) safe = NLORA - 1;

    float acc[4] = {0.f, 0.f, 0.f, 0.f};

    for (int c0 = 0; c0 < CIN; c0 += 16) {
        __syncthreads();
        for (int i = tid; i < 16 * 6 * PAD_HW; i += 256) {
            int c = i / (6 * PAD_HW);
            int rr = i - c * (6 * PAD_HW);
            int r = rr / PAD_HW, cl = rr - r * PAD_HW;
            int gh = h0 - 1 + r, gw = cl - 1;
            float v = 0.f;
            if ((unsigned)gh < (unsigned)H_ && (unsigned)gw < (unsigned)W_)
                v = x[((size_t)b * CIN + c0 + c) * 4096 + gh * 64 + gw];
            xs[c][r * PAD_HW + cl] = v;
        }
        for (int i = tid; i < 576; i += 256) {
            int c = i / 36, rem = i - c * 36;
            int tap = rem >> 2, r = rem & 3;
            ds[c][tap * 4 + r] = down_w[(((size_t)safe * RANK + r) * CIN + c0 + c) * 9 + tap];
        }
        __syncthreads();

        #pragma unroll 4
        for (int c = 0; c < 16; c++) {
            float4 dv[9];
            #pragma unroll
            for (int tap = 0; tap < 9; tap++) dv[tap] = *(const float4*)&ds[c][tap * 4];
            #pragma unroll
            for (int ky = 0; ky < 3; ky++) {
                #pragma unroll
                for (int kx = 0; kx < 3; kx++) {
                    float xv = xs[c][(hr + ky) * PAD_HW + w + kx];
                    float4 d = dv[ky * 3 + kx];
                    acc[0] += xv * d.x;
                    acc[1] += xv * d.y;
                    acc[2] += xv * d.z;
                    acc[3] += xv * d.w;
                }
            }
        }
    }
    const int pixel = mtile * 256 + tid;
    *(float4*)&g_down[((size_t)b * 4096 + pixel) * 4] = make_float4(acc[0], acc[1], acc[2], acc[3]);
}

// ---------------- main GEMM (mma.sync bf16, 3-way split) ----------------
#define NTH 256
#define AH_OFF 0
#define AL_OFF 16384
#define BH_OFF 32768
#define BL_OFF 53248
#define STAGE_SZ 73728
#define SM_UP   0
#define SM_BIAS 5120
#define SM_STG  8192
#define SMEM_SZ (SM_STG + 2 * STAGE_SZ)   // 155648

__device__ __forceinline__ void load_chunk(int q, uint32_t stg, int mtile, int nt, int b, int tid) {
    const int tap = q / 5, c0 = (q - tap * 5) * 64;
    const int ky = tap / 3, kx = tap - ky * 3;
    // A: 128 pixel rows x 64 bf16 (hi & lo)
    #pragma unroll 1
    for (int t = tid; t < 1024; t += NTH) {
        int row = t >> 3, sub = t & 7;
        int pi = row >> 6, cl = row & 63;
        int pp = (mtile * 2 + pi + ky) * PAD_HW + cl + kx;
        size_t off = ((size_t)b * PIX_PAD + pp) * CIN + c0 + sub * 8;
        uint32_t d = stg + (uint32_t)row * 128 + ((uint32_t)(sub ^ (row & 7)) << 4);
        CP16(d + AH_OFF, g_Xh + off);
        CP16(d + AL_OFF, g_Xl + off);
    }
    // B: 160 cout rows x 64 bf16 (hi & lo)
    #pragma unroll 1
    for (int t = tid; t < 1280; t += NTH) {
        int row = t >> 3, sub = t & 7;
        size_t off = (size_t)(nt * 160 + row) * KTOT + tap * CIN + c0 + sub * 8;
        uint32_t d = stg + (uint32_t)row * 128 + ((uint32_t)(sub ^ (row & 7)) << 4);
        CP16(d + BH_OFF, g_Wh + off);
        CP16(d + BL_OFF, g_Wl + off);
    }
}

__global__ __launch_bounds__(NTH)
void gemm_kernel(const float* __restrict__ conv_b, const float* __restrict__ up_w,
                 const int* __restrict__ lora_id, float* __restrict__ out) {
    extern __shared__ __align__(1024) char sm[];
    const uint32_t smb = smem_u32(sm);
    const int tid = threadIdx.x, wid = tid >> 5, lid = tid & 31;
    const int wm = wid & 3, wn = wid >> 2;           // warp grid 4(M) x 2(N)
    const int mtile = blockIdx.x;                    // 0..31
    const int nt    = blockIdx.y;                    // 0..1
    const int b     = blockIdx.z;

    const int idx = lora_id[b] / 4;
    const float sact = (idx >= 0) ? 1.f : 0.f;
    int safe = idx; if (safe < 0) safe = 0; if (safe > NLORA - 1) safe = NLORA - 1;

    float* up_s   = (float*)(sm + SM_UP);
    float* bias_s = (float*)(sm + SM_BIAS);
    for (int i = tid; i < COUT * RANK; i += NTH) up_s[i] = up_w[(size_t)safe * COUT * RANK + i];
    for (int i = tid; i < COUT; i += NTH) bias_s[i] = conv_b[i];

    float c[2][10][4];
    #pragma unroll
    for (int i = 0; i < 2; i++)
        #pragma unroll
        for (int j = 0; j < 10; j++)
            #pragma unroll
            for (int k = 0; k < 4; k++) c[i][j][k] = 0.f;

    // lane constants for ldmatrix addressing
    const int la7 = lid & 7, mq = lid >> 3;
    const uint32_t arow0 = (uint32_t)(wm * 32 + ((mq & 1) << 3) + la7) * 128;
    const uint32_t arow1 = arow0 + 16 * 128;
    const uint32_t acb = (uint32_t)(mq >> 1);
    uint32_t brow[5];
    #pragma unroll
    for (int jj = 0; jj < 5; jj++)
        brow[jj] = (uint32_t)(wn * 80 + jj * 16 + ((mq >> 1) << 3) + la7) * 128;
    const uint32_t bcb = (uint32_t)(mq & 1);

    load_chunk(0, smb + SM_STG, mtile, nt, b, tid);
    CPCOMMIT();

    #pragma unroll 1
    for (int q = 0; q < 45; q++) {
        const uint32_t stg = smb + SM_STG + (uint32_t)(q & 1) * STAGE_SZ;
        if (q + 1 < 45) {
            load_chunk(q + 1, smb + SM_STG + (uint32_t)((q + 1) & 1) * STAGE_SZ, mtile, nt, b, tid);
            CPCOMMIT();
            CPWAIT1();
        } else {
            CPWAIT0();
        }
        __syncthreads();

        #pragma unroll 1
        for (int s = 0; s < 3; s++) {
            const uint32_t aB = stg + ((s == 2) ? AL_OFF : AH_OFF);
            const uint32_t bB = stg + ((s == 1) ? BL_OFF : BH_OFF);
            #pragma unroll
            for (int kk = 0; kk < 4; kk++) {
                uint32_t a0[4], a1[4];
                const uint32_t ca = ((uint32_t)((kk * 2 + acb) ^ la7)) << 4;
                ldsm4(a0[0], a0[1], a0[2], a0[3], aB + arow0 + ca);
                ldsm4(a1[0], a1[1], a1[2], a1[3], aB + arow1 + ca);
                uint32_t bf[10][2];
                const uint32_t cb = ((uint32_t)((kk * 2 + bcb) ^ la7)) << 4;
                #pragma unroll
                for (int jj = 0; jj < 5; jj++)
                    ldsm4(bf[2 * jj][0], bf[2 * jj][1], bf[2 * jj + 1][0], bf[2 * jj + 1][1],
                          bB + brow[jj] + cb);    // non-trans: [n][k] rows ARE col-major k x n
                #pragma unroll
                for (int j = 0; j < 10; j++) {
                    mma_bf16(c[0][j][0], c[0][j][1], c[0][j][2], c[0][j][3],
                             a0[0], a0[1], a0[2], a0[3], bf[j][0], bf[j][1]);
                    mma_bf16(c[1][j][0], c[1][j][1], c[1][j][2], c[1][j][3],
                             a1[0], a1[1], a1[2], a1[3], bf[j][0], bf[j][1]);
                }
            }
        }
        __syncthreads();
    }

    // ---- epilogue: out = acc + bias + sact * up . down ----
    const int grp = lid >> 2, c2 = (lid & 3) * 2;
    #pragma unroll
    for (int i = 0; i < 2; i++) {
        #pragma unroll
        for (int rr = 0; rr < 2; rr++) {
            const int pixel = mtile * 128 + wm * 32 + i * 16 + rr * 8 + grp;
            float4 dv = *(const float4*)&g_down[((size_t)b * 4096 + pixel) * 4];
            dv.x *= sact; dv.y *= sact; dv.z *= sact; dv.w *= sact;
            #pragma unroll
            for (int j = 0; j < 10; j++) {
                const int ng = nt * 160 + wn * 80 + j * 8 + c2;
                const float4 u0 = *(const float4*)&up_s[ng * 4];
                const float4 u1 = *(const float4*)&up_s[(ng + 1) * 4];
                const float add0 = bias_s[ng]     + u0.x * dv.x + u0.y * dv.y + u0.z * dv.z + u0.w * dv.w;
                const float add1 = bias_s[ng + 1] + u1.x * dv.x + u1.y * dv.y + u1.z * dv.z + u1.w * dv.w;
                out[((size_t)(b * COUT + ng))     * 4096 + pixel] = c[i][j][rr * 2 + 0] + add0;
                out[((size_t)(b * COUT + ng + 1)) * 4096 + pixel] = c[i][j][rr * 2 + 1] + add1;
            }
        }
    }
}

// ---------------- launch ----------------
extern "C" void kernel_launch(void* const* d_in, const int* in_sizes, int n_in,
                              void* d_out, int out_size)
{
    const float* x       = (const float*)d_in[0];
    const float* conv_w  = (const float*)d_in[1];
    const float* conv_b  = (const float*)d_in[2];
    const float* down_w  = (const float*)d_in[3];
    const float* up_w    = (const float*)d_in[4];
    const int*   lora_id = (const int*)d_in[5];
    float* out = (float*)d_out;

    cudaFuncSetAttribute(convx_kernel, cudaFuncAttributeMaxDynamicSharedMemorySize, CIN * 65 * 4);
    cudaFuncSetAttribute(gemm_kernel,  cudaFuncAttributeMaxDynamicSharedMemorySize, SMEM_SZ);

    convx_kernel<<<dim3(H_, B_), 256, CIN * 65 * 4>>>(x);
    border_kernel<<<256, 256>>>();
    convw_kernel<<<400, 256>>>(conv_w);
    down_kernel<<<dim3(16, B_), 256>>>(x, down_w, lora_id);
    gemm_kernel<<<dim3(32, 2, B_), NTH, SMEM_SZ>>>(conv_b, up_w, lora_id, out);
}

// round 6
// speedup vs baseline: 5.7951x; 1.1339x over previous
#include <cuda_runtime.h>
#include <cuda_bf16.h>
#include <cstdint>

// ---------------- problem constants ----------------
#define B_      16
#define CIN     320
#define COUT    320
#define H_      64
#define W_      64
#define RANK    4
#define NLORA   50
#define KTOT    2880            // 9 taps * 320 cin
#define PAD_HW  66
#define PIX_PAD (PAD_HW * PAD_HW)

// ---------------- scratch ----------------
__device__ __align__(256) __nv_bfloat16 g_Xh[(size_t)B_ * PIX_PAD * CIN];
__device__ __align__(256) __nv_bfloat16 g_Xl[(size_t)B_ * PIX_PAD * CIN];
__device__ __align__(256) __nv_bfloat16 g_Wh[(size_t)COUT * KTOT];
__device__ __align__(256) __nv_bfloat16 g_Wl[(size_t)COUT * KTOT];
__device__ __align__(256) float        g_down[(size_t)4 * B_ * 4096 * 4];  // 4 cin-slices

// ---------------- PTX helpers (base ISA only) ----------------
__device__ __forceinline__ uint32_t smem_u32(const void* p) {
    uint32_t a;
    asm("{ .reg .u64 t; cvta.to.shared.u64 t, %1; cvt.u32.u64 %0, t; }" : "=r"(a) : "l"(p));
    return a;
}
#define CP16(dst, src) asm volatile("cp.async.cg.shared.global [%0], [%1], 16;" :: "r"(dst), "l"(src))
#define CPCOMMIT()     asm volatile("cp.async.commit_group;" ::: "memory")
#define CPWAIT0()      asm volatile("cp.async.wait_group 0;" ::: "memory")
#define CPWAIT1()      asm volatile("cp.async.wait_group 1;" ::: "memory")

__device__ __forceinline__ void ldsm4(uint32_t& r0, uint32_t& r1, uint32_t& r2, uint32_t& r3, uint32_t a) {
    asm volatile("ldmatrix.sync.aligned.m8n8.x4.shared.b16 {%0,%1,%2,%3},[%4];"
                 : "=r"(r0), "=r"(r1), "=r"(r2), "=r"(r3) : "r"(a));
}
__device__ __forceinline__ void mma_bf16(float& c0, float& c1, float& c2, float& c3,
                                         uint32_t a0, uint32_t a1, uint32_t a2, uint32_t a3,
                                         uint32_t b0, uint32_t b1) {
    asm volatile("mma.sync.aligned.m16n8k16.row.col.f32.bf16.bf16.f32 "
                 "{%0,%1,%2,%3},{%4,%5,%6,%7},{%8,%9},{%0,%1,%2,%3};"
                 : "+f"(c0), "+f"(c1), "+f"(c2), "+f"(c3)
                 : "r"(a0), "r"(a1), "r"(a2), "r"(a3), "r"(b0), "r"(b1));
}

// ---------------- convx: x[b,c,h,w] -> g_X{h,l}[b, padpix, c] ----------------
__global__ __launch_bounds__(256)
void convx_kernel(const float* __restrict__ x) {
    __shared__ uint4 s4[64][16];   // 64 c x 64 w, XOR-swizzled in 16B granules
    const int h = blockIdx.x, cc = blockIdx.y, b = blockIdx.z;
    const int c0 = cc * 64, tid = threadIdx.x;
    {
        const int c = tid >> 2, g0 = (tid & 3) * 4;
        const float* src = x + (((size_t)(b * CIN + c0 + c)) << 12) + h * 64;
        #pragma unroll
        for (int i = 0; i < 4; i++) {
            int g = g0 + i;
            s4[c][g ^ (c & 15)] = *(const uint4*)(src + g * 4);
        }
    }
    __syncthreads();
    const int wl = tid & 31, cg = tid >> 5;
    #pragma unroll
    for (int it = 0; it < 2; it++) {
        const int w = wl + it * 32;
        uint32_t hi[4], lo[4];
        #pragma unroll
        for (int j = 0; j < 8; j += 2) {
            const int ca = cg * 8 + j, cb = ca + 1;
            float va = ((const float*)&s4[ca][(w >> 2) ^ (ca & 15)])[w & 3];
            float vb = ((const float*)&s4[cb][(w >> 2) ^ (cb & 15)])[w & 3];
            __nv_bfloat16 ha = __float2bfloat16(va);
            __nv_bfloat16 hb = __float2bfloat16(vb);
            __nv_bfloat16 la = __float2bfloat16(va - __bfloat162float(ha));
            __nv_bfloat16 lb = __float2bfloat16(vb - __bfloat162float(hb));
            hi[j >> 1] = (uint32_t)*(uint16_t*)&ha | ((uint32_t)*(uint16_t*)&hb << 16);
            lo[j >> 1] = (uint32_t)*(uint16_t*)&la | ((uint32_t)*(uint16_t*)&lb << 16);
        }
        size_t base = ((size_t)b * PIX_PAD + (size_t)(h + 1) * PAD_HW + (w + 1)) * CIN + c0 + cg * 8;
        *(uint4*)&g_Xh[base] = make_uint4(hi[0], hi[1], hi[2], hi[3]);
        *(uint4*)&g_Xl[base] = make_uint4(lo[0], lo[1], lo[2], lo[3]);
    }
}

__global__ void border_kernel() {
    const int total = B_ * 260 * CIN;
    const __nv_bfloat16 z = __float2bfloat16(0.f);
    for (int i = blockIdx.x * blockDim.x + threadIdx.x; i < total; i += gridDim.x * blockDim.x) {
        int c = i % CIN, t = i / CIN;
        int bi = t % 260, b = t / 260;
        int pp;
        if (bi < 66)       pp = bi;
        else if (bi < 132) pp = 65 * PAD_HW + (bi - 66);
        else if (bi < 196) pp = (bi - 131) * PAD_HW;
        else               pp = (bi - 195) * PAD_HW + 65;
        size_t o = ((size_t)b * PIX_PAD + pp) * CIN + c;
        g_Xh[o] = z;
        g_Xl[o] = z;
    }
}

// conv_w[n, c, tap] -> g_W{h,l}[n, tap*320 + c]
__global__ void convw_kernel(const float* __restrict__ conv_w) {
    const int NW = COUT * CIN;
    for (int i = blockIdx.x * blockDim.x + threadIdx.x; i < NW; i += gridDim.x * blockDim.x) {
        int n = i / CIN, c = i - n * CIN;
        #pragma unroll
        for (int tap = 0; tap < 9; tap++) {
            float v = conv_w[((size_t)n * CIN + c) * 9 + tap];
            __nv_bfloat16 hi = __float2bfloat16(v);
            __nv_bfloat16 lo = __float2bfloat16(v - __bfloat162float(hi));
            size_t o = (size_t)n * KTOT + tap * CIN + c;
            g_Wh[o] = hi;
            g_Wl[o] = lo;
        }
    }
}

// ---------------- LoRA down conv (rank 4), cin sliced x4 ----------------
#define DS_CIN 80
__global__ __launch_bounds__(256)
void down_kernel(const float* __restrict__ x, const float* __restrict__ down_w,
                 const int* __restrict__ lora_id) {
    __shared__ float ds[DS_CIN][36];
    __shared__ float xs[16][416];          // 6 rows x stride 68; data idx 3..68 per row

    const int tid = threadIdx.x;
    const int mtile = blockIdx.x;          // 0..15 (4 h-rows)
    const int b = blockIdx.y;
    const int cs = blockIdx.z;             // 0..3
    const int cbase = cs * DS_CIN;
    const int h0 = mtile * 4, hr = tid >> 6, w = tid & 63;

    const int idx = lora_id[b] / 4;
    int safe = idx; if (safe < 0) safe = 0; if (safe > NLORA - 1) safe = NLORA - 1;

    for (int i = tid; i < DS_CIN * 36; i += 256) {
        int c = i / 36, rem = i - c * 36;
        int tap = rem >> 2, r = rem & 3;
        ds[c][tap * 4 + r] = down_w[(((size_t)safe * RANK + r) * CIN + cbase + c) * 9 + tap];
    }

    float acc[4] = {0.f, 0.f, 0.f, 0.f};

    for (int c0 = 0; c0 < DS_CIN; c0 += 16) {
        __syncthreads();
        // interior: 16c x 6rows x 16 float4 (w 0..63); halo cols are implicit zeros
        for (int i = tid; i < 16 * 6 * 16; i += 256) {
            int cr = i >> 4, v = i & 15;
            int c = cr / 6, r = cr - c * 6;
            int gh = h0 - 1 + r;
            float4 val = make_float4(0.f, 0.f, 0.f, 0.f);
            if ((unsigned)gh < 64u)
                val = *(const float4*)(x + (((size_t)(b * CIN + cbase + c0 + c)) << 12) + gh * 64 + v * 4);
            *(float4*)&xs[c][r * 68 + 4 + v * 4] = val;
        }
        for (int i = tid; i < 16 * 6; i += 256) {
            int c = i / 6, r = i - c * 6;
            xs[c][r * 68 + 3] = 0.f;
            xs[c][r * 68 + 68] = 0.f;
        }
        __syncthreads();

        #pragma unroll 2
        for (int c = 0; c < 16; c++) {
            #pragma unroll
            for (int ky = 0; ky < 3; ky++) {
                const float* row = &xs[c][(hr + ky) * 68 + 3 + w];
                float x0 = row[0], x1 = row[1], x2 = row[2];
                float4 d0 = *(const float4*)&ds[c0 + c][(ky * 3 + 0) * 4];
                float4 d1 = *(const float4*)&ds[c0 + c][(ky * 3 + 1) * 4];
                float4 d2 = *(const float4*)&ds[c0 + c][(ky * 3 + 2) * 4];
                acc[0] += x0 * d0.x + x1 * d1.x + x2 * d2.x;
                acc[1] += x0 * d0.y + x1 * d1.y + x2 * d2.y;
                acc[2] += x0 * d0.z + x1 * d1.z + x2 * d2.z;
                acc[3] += x0 * d0.w + x1 * d1.w + x2 * d2.w;
            }
        }
    }
    const int pixel = mtile * 256 + tid;   // (h0+hr)*64 + w
    *(float4*)&g_down[(((size_t)cs * B_ + b) * 4096 + pixel) * 4] =
        make_float4(acc[0], acc[1], acc[2], acc[3]);
}

// ---------------- main GEMM (mma.sync bf16, 3-way split, frag reuse) ----------------
#define NTH 256
#define AH_OFF 0
#define AL_OFF 16384
#define BH_OFF 32768
#define BL_OFF 53248
#define STAGE_SZ 73728
#define SM_UP   0
#define SM_BIAS 5120
#define SM_STG  8192
#define SMEM_SZ (SM_STG + 2 * STAGE_SZ)   // 155648

__device__ __forceinline__ void load_chunk(int q, uint32_t stg, int mtile, int nt, int b, int tid) {
    const int tap = q / 5, c0 = (q - tap * 5) * 64;
    const int ky = tap / 3, kx = tap - ky * 3;
    #pragma unroll 1
    for (int t = tid; t < 1024; t += NTH) {
        int row = t >> 3, sub = t & 7;
        int pi = row >> 6, cl = row & 63;
        int pp = (mtile * 2 + pi + ky) * PAD_HW + cl + kx;
        size_t off = ((size_t)b * PIX_PAD + pp) * CIN + c0 + sub * 8;
        uint32_t d = stg + (uint32_t)row * 128 + ((uint32_t)(sub ^ (row & 7)) << 4);
        CP16(d + AH_OFF, g_Xh + off);
        CP16(d + AL_OFF, g_Xl + off);
    }
    #pragma unroll 1
    for (int t = tid; t < 1280; t += NTH) {
        int row = t >> 3, sub = t & 7;
        size_t off = (size_t)(nt * 160 + row) * KTOT + tap * CIN + c0 + sub * 8;
        uint32_t d = stg + (uint32_t)row * 128 + ((uint32_t)(sub ^ (row & 7)) << 4);
        CP16(d + BH_OFF, g_Wh + off);
        CP16(d + BL_OFF, g_Wl + off);
    }
}

__global__ __launch_bounds__(NTH)
void gemm_kernel(const float* __restrict__ conv_b, const float* __restrict__ up_w,
                 const int* __restrict__ lora_id, float* __restrict__ out) {
    extern __shared__ __align__(1024) char sm[];
    const uint32_t smb = smem_u32(sm);
    const int tid = threadIdx.x, wid = tid >> 5, lid = tid & 31;
    const int wm = wid & 3, wn = wid >> 2;
    const int mtile = blockIdx.x;
    const int nt    = blockIdx.y;
    const int b     = blockIdx.z;

    const int idx = lora_id[b] / 4;
    const float sact = (idx >= 0) ? 1.f : 0.f;
    int safe = idx; if (safe < 0) safe = 0; if (safe > NLORA - 1) safe = NLORA - 1;

    float* up_s   = (float*)(sm + SM_UP);
    float* bias_s = (float*)(sm + SM_BIAS);
    for (int i = tid; i < COUT * RANK; i += NTH) up_s[i] = up_w[(size_t)safe * COUT * RANK + i];
    for (int i = tid; i < COUT; i += NTH) bias_s[i] = conv_b[i];

    float c[2][10][4];
    #pragma unroll
    for (int i = 0; i < 2; i++)
        #pragma unroll
        for (int j = 0; j < 10; j++)
            #pragma unroll
            for (int k = 0; k < 4; k++) c[i][j][k] = 0.f;

    const int la7 = lid & 7, mq = lid >> 3;
    const uint32_t arow0 = (uint32_t)(wm * 32 + ((mq & 1) << 3) + la7) * 128;
    const uint32_t arow1 = arow0 + 16 * 128;
    const uint32_t acb = (uint32_t)(mq >> 1);
    uint32_t brow[5];
    #pragma unroll
    for (int jj = 0; jj < 5; jj++)
        brow[jj] = (uint32_t)(wn * 80 + jj * 16 + ((mq >> 1) << 3) + la7) * 128;
    const uint32_t bcb = (uint32_t)(mq & 1);

    load_chunk(0, smb + SM_STG, mtile, nt, b, tid);
    CPCOMMIT();

    #pragma unroll 1
    for (int q = 0; q < 45; q++) {
        const uint32_t stg = smb + SM_STG + (uint32_t)(q & 1) * STAGE_SZ;
        if (q + 1 < 45) {
            load_chunk(q + 1, smb + SM_STG + (uint32_t)((q + 1) & 1) * STAGE_SZ, mtile, nt, b, tid);
            CPCOMMIT();
            CPWAIT1();
        } else {
            CPWAIT0();
        }
        __syncthreads();

        const uint32_t aH = stg + AH_OFF, aL = stg + AL_OFF;
        const uint32_t bH = stg + BH_OFF, bL = stg + BL_OFF;
        #pragma unroll
        for (int kk = 0; kk < 4; kk++) {
            const uint32_t ca = ((uint32_t)((kk * 2 + acb) ^ la7)) << 4;
            const uint32_t cb = ((uint32_t)((kk * 2 + bcb) ^ la7)) << 4;
            uint32_t ah0[4], ah1[4], al0[4], al1[4];
            ldsm4(ah0[0], ah0[1], ah0[2], ah0[3], aH + arow0 + ca);
            ldsm4(ah1[0], ah1[1], ah1[2], ah1[3], aH + arow1 + ca);
            ldsm4(al0[0], al0[1], al0[2], al0[3], aL + arow0 + ca);
            ldsm4(al1[0], al1[1], al1[2], al1[3], aL + arow1 + ca);
            uint32_t bh[10][2], bl[10][2];
            #pragma unroll
            for (int jj = 0; jj < 5; jj++)
                ldsm4(bh[2 * jj][0], bh[2 * jj][1], bh[2 * jj + 1][0], bh[2 * jj + 1][1],
                      bH + brow[jj] + cb);
            #pragma unroll
            for (int jj = 0; jj < 5; jj++)
                ldsm4(bl[2 * jj][0], bl[2 * jj][1], bl[2 * jj + 1][0], bl[2 * jj + 1][1],
                      bL + brow[jj] + cb);
            // hh
            #pragma unroll
            for (int j = 0; j < 10; j++) {
                mma_bf16(c[0][j][0], c[0][j][1], c[0][j][2], c[0][j][3],
                         ah0[0], ah0[1], ah0[2], ah0[3], bh[j][0], bh[j][1]);
                mma_bf16(c[1][j][0], c[1][j][1], c[1][j][2], c[1][j][3],
                         ah1[0], ah1[1], ah1[2], ah1[3], bh[j][0], bh[j][1]);
            }
            // hl
            #pragma unroll
            for (int j = 0; j < 10; j++) {
                mma_bf16(c[0][j][0], c[0][j][1], c[0][j][2], c[0][j][3],
                         ah0[0], ah0[1], ah0[2], ah0[3], bl[j][0], bl[j][1]);
                mma_bf16(c[1][j][0], c[1][j][1], c[1][j][2], c[1][j][3],
                         ah1[0], ah1[1], ah1[2], ah1[3], bl[j][0], bl[j][1]);
            }
            // lh
            #pragma unroll
            for (int j = 0; j < 10; j++) {
                mma_bf16(c[0][j][0], c[0][j][1], c[0][j][2], c[0][j][3],
                         al0[0], al0[1], al0[2], al0[3], bh[j][0], bh[j][1]);
                mma_bf16(c[1][j][0], c[1][j][1], c[1][j][2], c[1][j][3],
                         al1[0], al1[1], al1[2], al1[3], bh[j][0], bh[j][1]);
            }
        }
        __syncthreads();
    }

    // ---- epilogue: out = acc + bias + sact * up . (sum of 4 down slices) ----
    const int grp = lid >> 2, c2 = (lid & 3) * 2;
    #pragma unroll
    for (int i = 0; i < 2; i++) {
        #pragma unroll
        for (int rr = 0; rr < 2; rr++) {
            const int pixel = mtile * 128 + wm * 32 + i * 16 + rr * 8 + grp;
            float4 dv = make_float4(0.f, 0.f, 0.f, 0.f);
            #pragma unroll
            for (int s = 0; s < 4; s++) {
                float4 t = *(const float4*)&g_down[(((size_t)s * B_ + b) * 4096 + pixel) * 4];
                dv.x += t.x; dv.y += t.y; dv.z += t.z; dv.w += t.w;
            }
            dv.x *= sact; dv.y *= sact; dv.z *= sact; dv.w *= sact;
            #pragma unroll
            for (int j = 0; j < 10; j++) {
                const int ng = nt * 160 + wn * 80 + j * 8 + c2;
                const float4 u0 = *(const float4*)&up_s[ng * 4];
                const float4 u1 = *(const float4*)&up_s[(ng + 1) * 4];
                const float add0 = bias_s[ng]     + u0.x * dv.x + u0.y * dv.y + u0.z * dv.z + u0.w * dv.w;
                const float add1 = bias_s[ng + 1] + u1.x * dv.x + u1.y * dv.y + u1.z * dv.z + u1.w * dv.w;
                out[((size_t)(b * COUT + ng))     * 4096 + pixel] = c[i][j][rr * 2 + 0] + add0;
                out[((size_t)(b * COUT + ng + 1)) * 4096 + pixel] = c[i][j][rr * 2 + 1] + add1;
            }
        }
    }
}

// ---------------- launch ----------------
extern "C" void kernel_launch(void* const* d_in, const int* in_sizes, int n_in,
                              void* d_out, int out_size)
{
    const float* x       = (const float*)d_in[0];
    const float* conv_w  = (const float*)d_in[1];
    const float* conv_b  = (const float*)d_in[2];
    const float* down_w  = (const float*)d_in[3];
    const float* up_w    = (const float*)d_in[4];
    const int*   lora_id = (const int*)d_in[5];
    float* out = (float*)d_out;

    cudaFuncSetAttribute(gemm_kernel, cudaFuncAttributeMaxDynamicSharedMemorySize, SMEM_SZ);

    convx_kernel<<<dim3(H_, 5, B_), 256>>>(x);
    border_kernel<<<256, 256>>>();
    convw_kernel<<<400, 256>>>(conv_w);
    down_kernel<<<dim3(16, B_, 4), 256>>>(x, down_w, lora_id);
    gemm_kernel<<<dim3(32, 2, B_), NTH, SMEM_SZ>>>(conv_b, up_w, lora_id, out);
}

// round 7
// speedup vs baseline: 10.8415x; 1.8708x over previous
#include <cuda_runtime.h>
#include <cuda_fp16.h>
#include <cstdint>

// ---------------- problem constants ----------------
#define B_      16
#define CIN     320
#define COUT    320
#define H_      64
#define W_      64
#define RANK    4
#define NLORA   50
#define KTOT    2880            // 9 taps * 320 cin
#define PAD_HW  66
#define PIX_PAD (PAD_HW * PAD_HW)

// ---------------- scratch ----------------
__device__ __align__(256) __half g_X[(size_t)B_ * PIX_PAD * CIN];   // padded, transposed x (fp16)
__device__ __align__(256) __half g_W[(size_t)COUT * KTOT];          // weights (fp16)
__device__ __align__(256) float  g_down[(size_t)4 * B_ * 4096 * 4]; // 4 cin-slices

// ---------------- PTX helpers (base ISA only) ----------------
__device__ __forceinline__ uint32_t smem_u32(const void* p) {
    uint32_t a;
    asm("{ .reg .u64 t; cvta.to.shared.u64 t, %1; cvt.u32.u64 %0, t; }" : "=r"(a) : "l"(p));
    return a;
}
#define CP16(dst, src) asm volatile("cp.async.cg.shared.global [%0], [%1], 16;" :: "r"(dst), "l"(src))
#define CPCOMMIT()     asm volatile("cp.async.commit_group;" ::: "memory")
#define CPWAIT0()      asm volatile("cp.async.wait_group 0;" ::: "memory")
#define CPWAIT1()      asm volatile("cp.async.wait_group 1;" ::: "memory")

__device__ __forceinline__ void ldsm4(uint32_t& r0, uint32_t& r1, uint32_t& r2, uint32_t& r3, uint32_t a) {
    asm volatile("ldmatrix.sync.aligned.m8n8.x4.shared.b16 {%0,%1,%2,%3},[%4];"
                 : "=r"(r0), "=r"(r1), "=r"(r2), "=r"(r3) : "r"(a));
}
__device__ __forceinline__ void mma_fp16(float& c0, float& c1, float& c2, float& c3,
                                         uint32_t a0, uint32_t a1, uint32_t a2, uint32_t a3,
                                         uint32_t b0, uint32_t b1) {
    asm volatile("mma.sync.aligned.m16n8k16.row.col.f32.f16.f16.f32 "
                 "{%0,%1,%2,%3},{%4,%5,%6,%7},{%8,%9},{%0,%1,%2,%3};"
                 : "+f"(c0), "+f"(c1), "+f"(c2), "+f"(c3)
                 : "r"(a0), "r"(a1), "r"(a2), "r"(a3), "r"(b0), "r"(b1));
}

// ---------------- convx: x[b,c,h,w] fp32 -> g_X[b, padpix, c] fp16 ----------------
__global__ __launch_bounds__(256)
void convx_kernel(const float* __restrict__ x) {
    __shared__ uint4 s4[64][16];   // 64 c x 64 w, XOR-swizzled in 16B granules
    const int h = blockIdx.x, cc = blockIdx.y, b = blockIdx.z;
    const int c0 = cc * 64, tid = threadIdx.x;
    {
        const int c = tid >> 2, g0 = (tid & 3) * 4;
        const float* src = x + (((size_t)(b * CIN + c0 + c)) << 12) + h * 64;
        #pragma unroll
        for (int i = 0; i < 4; i++) {
            int g = g0 + i;
            s4[c][g ^ (c & 15)] = *(const uint4*)(src + g * 4);
        }
    }
    __syncthreads();
    const int wl = tid & 31, cg = tid >> 5;
    #pragma unroll
    for (int it = 0; it < 2; it++) {
        const int w = wl + it * 32;
        uint32_t hv[4];
        #pragma unroll
        for (int j = 0; j < 8; j += 2) {
            const int ca = cg * 8 + j, cb = ca + 1;
            float va = ((const float*)&s4[ca][(w >> 2) ^ (ca & 15)])[w & 3];
            float vb = ((const float*)&s4[cb][(w >> 2) ^ (cb & 15)])[w & 3];
            __half ha = __float2half_rn(va);
            __half hb = __float2half_rn(vb);
            hv[j >> 1] = (uint32_t)*(uint16_t*)&ha | ((uint32_t)*(uint16_t*)&hb << 16);
        }
        size_t base = ((size_t)b * PIX_PAD + (size_t)(h + 1) * PAD_HW + (w + 1)) * CIN + c0 + cg * 8;
        *(uint4*)&g_X[base] = make_uint4(hv[0], hv[1], hv[2], hv[3]);
    }
}

__global__ void border_kernel() {
    const int total = B_ * 260 * CIN;
    const __half z = __float2half_rn(0.f);
    for (int i = blockIdx.x * blockDim.x + threadIdx.x; i < total; i += gridDim.x * blockDim.x) {
        int c = i % CIN, t = i / CIN;
        int bi = t % 260, b = t / 260;
        int pp;
        if (bi < 66)       pp = bi;
        else if (bi < 132) pp = 65 * PAD_HW + (bi - 66);
        else if (bi < 196) pp = (bi - 131) * PAD_HW;
        else               pp = (bi - 195) * PAD_HW + 65;
        g_X[((size_t)b * PIX_PAD + pp) * CIN + c] = z;
    }
}

// conv_w[n, c, tap] -> g_W[n, tap*320 + c]
__global__ void convw_kernel(const float* __restrict__ conv_w) {
    const int NW = COUT * CIN;
    for (int i = blockIdx.x * blockDim.x + threadIdx.x; i < NW; i += gridDim.x * blockDim.x) {
        int n = i / CIN, c = i - n * CIN;
        #pragma unroll
        for (int tap = 0; tap < 9; tap++) {
            float v = conv_w[((size_t)n * CIN + c) * 9 + tap];
            g_W[(size_t)n * KTOT + tap * CIN + c] = __float2half_rn(v);
        }
    }
}

// ---------------- LoRA down conv (rank 4, fp32), cin sliced x4 ----------------
#define DS_CIN 80
__global__ __launch_bounds__(256)
void down_kernel(const float* __restrict__ x, const float* __restrict__ down_w,
                 const int* __restrict__ lora_id) {
    __shared__ float ds[DS_CIN][36];
    __shared__ float xs[8][10 * 72];       // 8 cin x 10 rows x stride 72 (interior idx 4..67)

    const int tid = threadIdx.x;
    const int mtile = blockIdx.x;          // 0..7 (8 h-rows each)
    const int b = blockIdx.y;
    const int cs = blockIdx.z;             // 0..3
    const int cbase = cs * DS_CIN;
    const int h0 = mtile * 8;
    const int hr = tid >> 5;               // 0..7
    const int w0 = (tid & 31) * 2;         // 0,2,..,62

    const int idx = lora_id[b] / 4;
    int safe = idx; if (safe < 0) safe = 0; if (safe > NLORA - 1) safe = NLORA - 1;

    for (int i = tid; i < DS_CIN * 36; i += 256) {
        int c = i / 36, rem = i - c * 36;
        int tap = rem >> 2, r = rem & 3;
        ds[c][tap * 4 + r] = down_w[(((size_t)safe * RANK + r) * CIN + cbase + c) * 9 + tap];
    }

    float acc[2][4];
    #pragma unroll
    for (int p = 0; p < 2; p++)
        #pragma unroll
        for (int r = 0; r < 4; r++) acc[p][r] = 0.f;

    for (int c0 = 0; c0 < DS_CIN; c0 += 8) {
        __syncthreads();
        // interior: 8c x 10r x 16 float4
        for (int i = tid; i < 1280; i += 256) {
            int v = i & 15, cr = i >> 4;
            int c = cr / 10, r = cr - c * 10;
            int gh = h0 - 1 + r;
            float4 val = make_float4(0.f, 0.f, 0.f, 0.f);
            if ((unsigned)gh < 64u)
                val = *(const float4*)(x + (((size_t)(b * CIN + cbase + c0 + c)) << 12) + gh * 64 + v * 4);
            *(float4*)&xs[c][r * 72 + 4 + v * 4] = val;
        }
        for (int i = tid; i < 80; i += 256) {
            int c = i / 10, r = i - c * 10;
            xs[c][r * 72 + 3] = 0.f;
            xs[c][r * 72 + 68] = 0.f;
        }
        __syncthreads();

        #pragma unroll 2
        for (int c = 0; c < 8; c++) {
            float4 dv[9];
            #pragma unroll
            for (int tap = 0; tap < 9; tap++) dv[tap] = *(const float4*)&ds[c0 + c][tap * 4];
            #pragma unroll
            for (int ky = 0; ky < 3; ky++) {
                const float* row = &xs[c][(hr + ky) * 72 + 3 + w0];   // row[g] = x[w0-1+g]
                float x4[4];
                #pragma unroll
                for (int g = 0; g < 4; g++) x4[g] = row[g];
                #pragma unroll
                for (int kx = 0; kx < 3; kx++) {
                    const float4 d = dv[ky * 3 + kx];
                    const float p0 = x4[kx], p1 = x4[kx + 1];
                    acc[0][0] += p0 * d.x; acc[0][1] += p0 * d.y;
                    acc[0][2] += p0 * d.z; acc[0][3] += p0 * d.w;
                    acc[1][0] += p1 * d.x; acc[1][1] += p1 * d.y;
                    acc[1][2] += p1 * d.z; acc[1][3] += p1 * d.w;
                }
            }
        }
    }
    const int pixel = (h0 + hr) * 64 + w0;
    float* dst = &g_down[(((size_t)cs * B_ + b) * 4096 + pixel) * 4];
    *(float4*)dst       = make_float4(acc[0][0], acc[0][1], acc[0][2], acc[0][3]);
    *(float4*)(dst + 4) = make_float4(acc[1][0], acc[1][1], acc[1][2], acc[1][3]);
}

// ---------------- main GEMM (mma.sync fp16, single pass) ----------------
#define NTH 256
#define A_OFF 0
#define B_OFF 16384
#define STAGE_SZ 36864
#define SM_UP   0
#define SM_BIAS 5120
#define SM_STG  8192
#define SMEM_SZ (SM_STG + 2 * STAGE_SZ)   // 81920

__device__ __forceinline__ void load_chunk(int q, uint32_t stg, int mtile, int nt, int b, int tid) {
    const int tap = q / 5, c0 = (q - tap * 5) * 64;
    const int ky = tap / 3, kx = tap - ky * 3;
    // A: 128 pixel rows x 64 fp16
    #pragma unroll 1
    for (int t = tid; t < 1024; t += NTH) {
        int row = t >> 3, sub = t & 7;
        int pi = row >> 6, cl = row & 63;
        int pp = (mtile * 2 + pi + ky) * PAD_HW + cl + kx;
        size_t off = ((size_t)b * PIX_PAD + pp) * CIN + c0 + sub * 8;
        uint32_t d = stg + A_OFF + (uint32_t)row * 128 + ((uint32_t)(sub ^ (row & 7)) << 4);
        CP16(d, g_X + off);
    }
    // B: 160 cout rows x 64 fp16
    #pragma unroll 1
    for (int t = tid; t < 1280; t += NTH) {
        int row = t >> 3, sub = t & 7;
        size_t off = (size_t)(nt * 160 + row) * KTOT + tap * CIN + c0 + sub * 8;
        uint32_t d = stg + B_OFF + (uint32_t)row * 128 + ((uint32_t)(sub ^ (row & 7)) << 4);
        CP16(d, g_W + off);
    }
}

__global__ __launch_bounds__(NTH)
void gemm_kernel(const float* __restrict__ conv_b, const float* __restrict__ up_w,
                 const int* __restrict__ lora_id, float* __restrict__ out) {
    extern __shared__ __align__(1024) char sm[];
    const uint32_t smb = smem_u32(sm);
    const int tid = threadIdx.x, wid = tid >> 5, lid = tid & 31;
    const int wm = wid & 3, wn = wid >> 2;
    const int mtile = blockIdx.x;
    const int nt    = blockIdx.y;
    const int b     = blockIdx.z;

    const int idx = lora_id[b] / 4;
    const float sact = (idx >= 0) ? 1.f : 0.f;
    int safe = idx; if (safe < 0) safe = 0; if (safe > NLORA - 1) safe = NLORA - 1;

    float* up_s   = (float*)(sm + SM_UP);
    float* bias_s = (float*)(sm + SM_BIAS);
    for (int i = tid; i < COUT * RANK; i += NTH) up_s[i] = up_w[(size_t)safe * COUT * RANK + i];
    for (int i = tid; i < COUT; i += NTH) bias_s[i] = conv_b[i];

    float c[2][10][4];
    #pragma unroll
    for (int i = 0; i < 2; i++)
        #pragma unroll
        for (int j = 0; j < 10; j++)
            #pragma unroll
            for (int k = 0; k < 4; k++) c[i][j][k] = 0.f;

    const int la7 = lid & 7, mq = lid >> 3;
    const uint32_t arow0 = (uint32_t)(wm * 32 + ((mq & 1) << 3) + la7) * 128;
    const uint32_t arow1 = arow0 + 16 * 128;
    const uint32_t acb = (uint32_t)(mq >> 1);
    uint32_t brow[5];
    #pragma unroll
    for (int jj = 0; jj < 5; jj++)
        brow[jj] = (uint32_t)(wn * 80 + jj * 16 + ((mq >> 1) << 3) + la7) * 128;
    const uint32_t bcb = (uint32_t)(mq & 1);

    load_chunk(0, smb + SM_STG, mtile, nt, b, tid);
    CPCOMMIT();

    #pragma unroll 1
    for (int q = 0; q < 45; q++) {
        const uint32_t stg = smb + SM_STG + (uint32_t)(q & 1) * STAGE_SZ;
        if (q + 1 < 45) {
            load_chunk(q + 1, smb + SM_STG + (uint32_t)((q + 1) & 1) * STAGE_SZ, mtile, nt, b, tid);
            CPCOMMIT();
            CPWAIT1();
        } else {
            CPWAIT0();
        }
        __syncthreads();

        const uint32_t aB = stg + A_OFF, bB = stg + B_OFF;
        #pragma unroll
        for (int kk = 0; kk < 4; kk++) {
            const uint32_t ca = ((uint32_t)((kk * 2 + acb) ^ la7)) << 4;
            const uint32_t cb = ((uint32_t)((kk * 2 + bcb) ^ la7)) << 4;
            uint32_t a0[4], a1[4];
            ldsm4(a0[0], a0[1], a0[2], a0[3], aB + arow0 + ca);
            ldsm4(a1[0], a1[1], a1[2], a1[3], aB + arow1 + ca);
            uint32_t bf[10][2];
            #pragma unroll
            for (int jj = 0; jj < 5; jj++)
                ldsm4(bf[2 * jj][0], bf[2 * jj][1], bf[2 * jj + 1][0], bf[2 * jj + 1][1],
                      bB + brow[jj] + cb);    // non-trans: [n][k] rows ARE col-major k x n
            #pragma unroll
            for (int j = 0; j < 10; j++) {
                mma_fp16(c[0][j][0], c[0][j][1], c[0][j][2], c[0][j][3],
                         a0[0], a0[1], a0[2], a0[3], bf[j][0], bf[j][1]);
                mma_fp16(c[1][j][0], c[1][j][1], c[1][j][2], c[1][j][3],
                         a1[0], a1[1], a1[2], a1[3], bf[j][0], bf[j][1]);
            }
        }
        __syncthreads();
    }

    // ---- epilogue: out = acc + bias + sact * up . (sum of 4 down slices) ----
    const int grp = lid >> 2, c2 = (lid & 3) * 2;
    #pragma unroll
    for (int i = 0; i < 2; i++) {
        #pragma unroll
        for (int rr = 0; rr < 2; rr++) {
            const int pixel = mtile * 128 + wm * 32 + i * 16 + rr * 8 + grp;
            float4 dv = make_float4(0.f, 0.f, 0.f, 0.f);
            #pragma unroll
            for (int s = 0; s < 4; s++) {
                float4 t = *(const float4*)&g_down[(((size_t)s * B_ + b) * 4096 + pixel) * 4];
                dv.x += t.x; dv.y += t.y; dv.z += t.z; dv.w += t.w;
            }
            dv.x *= sact; dv.y *= sact; dv.z *= sact; dv.w *= sact;
            #pragma unroll
            for (int j = 0; j < 10; j++) {
                const int ng = nt * 160 + wn * 80 + j * 8 + c2;
                const float4 u0 = *(const float4*)&up_s[ng * 4];
                const float4 u1 = *(const float4*)&up_s[(ng + 1) * 4];
                const float add0 = bias_s[ng]     + u0.x * dv.x + u0.y * dv.y + u0.z * dv.z + u0.w * dv.w;
                const float add1 = bias_s[ng + 1] + u1.x * dv.x + u1.y * dv.y + u1.z * dv.z + u1.w * dv.w;
                out[((size_t)(b * COUT + ng))     * 4096 + pixel] = c[i][j][rr * 2 + 0] + add0;
                out[((size_t)(b * COUT + ng + 1)) * 4096 + pixel] = c[i][j][rr * 2 + 1] + add1;
            }
        }
    }
}

// ---------------- launch ----------------
extern "C" void kernel_launch(void* const* d_in, const int* in_sizes, int n_in,
                              void* d_out, int out_size)
{
    const float* x       = (const float*)d_in[0];
    const float* conv_w  = (const float*)d_in[1];
    const float* conv_b  = (const float*)d_in[2];
    const float* down_w  = (const float*)d_in[3];
    const float* up_w    = (const float*)d_in[4];
    const int*   lora_id = (const int*)d_in[5];
    float* out = (float*)d_out;

    cudaFuncSetAttribute(gemm_kernel, cudaFuncAttributeMaxDynamicSharedMemorySize, SMEM_SZ);

    convx_kernel<<<dim3(H_, 5, B_), 256>>>(x);
    border_kernel<<<256, 256>>>();
    convw_kernel<<<400, 256>>>(conv_w);
    down_kernel<<<dim3(8, B_, 4), 256>>>(x, down_w, lora_id);
    gemm_kernel<<<dim3(32, 2, B_), NTH, SMEM_SZ>>>(conv_b, up_w, lora_id, out);
}

// round 8
// speedup vs baseline: 11.9643x; 1.1036x over previous
#include <cuda_runtime.h>
#include <cuda_fp16.h>
#include <cstdint>

// ---------------- problem constants ----------------
#define B_      16
#define CIN     320
#define COUT    320
#define H_      64
#define W_      64
#define RANK    4
#define NLORA   50
#define KTOT    2880            // 9 taps * 320 cin
#define PAD_HW  66
#define PIX_PAD (PAD_HW * PAD_HW)

// ---------------- scratch ----------------
__device__ __align__(256) __half g_X[(size_t)B_ * PIX_PAD * CIN];   // padded, transposed x (fp16)
__device__ __align__(256) __half g_W[(size_t)COUT * KTOT];          // base weights (fp16)
__device__ __align__(256) __half g_D[(size_t)NLORA * 8 * KTOT];     // down weights, 8 rank rows (4 zero)

// ---------------- PTX helpers (base ISA only) ----------------
__device__ __forceinline__ uint32_t smem_u32(const void* p) {
    uint32_t a;
    asm("{ .reg .u64 t; cvta.to.shared.u64 t, %1; cvt.u32.u64 %0, t; }" : "=r"(a) : "l"(p));
    return a;
}
#define CP16(dst, src) asm volatile("cp.async.cg.shared.global [%0], [%1], 16;" :: "r"(dst), "l"(src))
#define CPCOMMIT()     asm volatile("cp.async.commit_group;" ::: "memory")
#define CPWAIT0()      asm volatile("cp.async.wait_group 0;" ::: "memory")
#define CPWAIT1()      asm volatile("cp.async.wait_group 1;" ::: "memory")

__device__ __forceinline__ void ldsm4(uint32_t& r0, uint32_t& r1, uint32_t& r2, uint32_t& r3, uint32_t a) {
    asm volatile("ldmatrix.sync.aligned.m8n8.x4.shared.b16 {%0,%1,%2,%3},[%4];"
                 : "=r"(r0), "=r"(r1), "=r"(r2), "=r"(r3) : "r"(a));
}
__device__ __forceinline__ void ldsm2(uint32_t& r0, uint32_t& r1, uint32_t a) {
    asm volatile("ldmatrix.sync.aligned.m8n8.x2.shared.b16 {%0,%1},[%2];"
                 : "=r"(r0), "=r"(r1) : "r"(a));
}
__device__ __forceinline__ void mma_fp16(float& c0, float& c1, float& c2, float& c3,
                                         uint32_t a0, uint32_t a1, uint32_t a2, uint32_t a3,
                                         uint32_t b0, uint32_t b1) {
    asm volatile("mma.sync.aligned.m16n8k16.row.col.f32.f16.f16.f32 "
                 "{%0,%1,%2,%3},{%4,%5,%6,%7},{%8,%9},{%0,%1,%2,%3};"
                 : "+f"(c0), "+f"(c1), "+f"(c2), "+f"(c3)
                 : "r"(a0), "r"(a1), "r"(a2), "r"(a3), "r"(b0), "r"(b1));
}

// ---------------- convx: x[b,c,h,w] fp32 -> g_X[b, padpix, c] fp16 ----------------
__global__ __launch_bounds__(256)
void convx_kernel(const float* __restrict__ x) {
    __shared__ uint4 s4[64][16];   // 64 c x 64 w, XOR-swizzled in 16B granules
    const int h = blockIdx.x, cc = blockIdx.y, b = blockIdx.z;
    const int c0 = cc * 64, tid = threadIdx.x;
    {
        const int c = tid >> 2, g0 = (tid & 3) * 4;
        const float* src = x + (((size_t)(b * CIN + c0 + c)) << 12) + h * 64;
        #pragma unroll
        for (int i = 0; i < 4; i++) {
            int g = g0 + i;
            s4[c][g ^ (c & 15)] = *(const uint4*)(src + g * 4);
        }
    }
    __syncthreads();
    const int wl = tid & 31, cg = tid >> 5;
    #pragma unroll
    for (int it = 0; it < 2; it++) {
        const int w = wl + it * 32;
        uint32_t hv[4];
        #pragma unroll
        for (int j = 0; j < 8; j += 2) {
            const int ca = cg * 8 + j, cb = ca + 1;
            float va = ((const float*)&s4[ca][(w >> 2) ^ (ca & 15)])[w & 3];
            float vb = ((const float*)&s4[cb][(w >> 2) ^ (cb & 15)])[w & 3];
            __half ha = __float2half_rn(va);
            __half hb = __float2half_rn(vb);
            hv[j >> 1] = (uint32_t)*(uint16_t*)&ha | ((uint32_t)*(uint16_t*)&hb << 16);
        }
        size_t base = ((size_t)b * PIX_PAD + (size_t)(h + 1) * PAD_HW + (w + 1)) * CIN + c0 + cg * 8;
        *(uint4*)&g_X[base] = make_uint4(hv[0], hv[1], hv[2], hv[3]);
    }
}

__global__ void border_kernel() {
    const int total = B_ * 260 * CIN;
    const __half z = __float2half_rn(0.f);
    for (int i = blockIdx.x * blockDim.x + threadIdx.x; i < total; i += gridDim.x * blockDim.x) {
        int c = i % CIN, t = i / CIN;
        int bi = t % 260, b = t / 260;
        int pp;
        if (bi < 66)       pp = bi;
        else if (bi < 132) pp = 65 * PAD_HW + (bi - 66);
        else if (bi < 196) pp = (bi - 131) * PAD_HW;
        else               pp = (bi - 195) * PAD_HW + 65;
        g_X[((size_t)b * PIX_PAD + pp) * CIN + c] = z;
    }
}

// conv_w[n, c, tap] -> g_W[n, tap*320+c];  down_w[l, r, c, tap] -> g_D[l*8+r, tap*320+c]
__global__ void convw_kernel(const float* __restrict__ conv_w, const float* __restrict__ down_w) {
    const int NW = COUT * CIN;                 // 102400
    const int ND = NLORA * 8 * CIN;            // 128000
    for (int i = blockIdx.x * blockDim.x + threadIdx.x; i < NW + ND; i += gridDim.x * blockDim.x) {
        if (i < NW) {
            int n = i / CIN, c = i - n * CIN;
            #pragma unroll
            for (int tap = 0; tap < 9; tap++) {
                float v = conv_w[((size_t)n * CIN + c) * 9 + tap];
                g_W[(size_t)n * KTOT + tap * CIN + c] = __float2half_rn(v);
            }
        } else {
            int j = i - NW;
            int c = j % CIN, t = j / CIN;
            int r = t % 8, l = t / 8;
            #pragma unroll
            for (int tap = 0; tap < 9; tap++) {
                float v = 0.f;
                if (r < RANK)
                    v = down_w[(((size_t)l * RANK + r) * CIN + c) * 9 + tap];
                g_D[((size_t)l * 8 + r) * KTOT + tap * CIN + c] = __float2half_rn(v);
            }
        }
    }
}

// ---------------- main GEMM (mma.sync fp16, down conv fused) ----------------
#define NTH 256
#define A_OFF  0
#define B_OFF  16384
#define BD_OFF 36864
#define STAGE_SZ 37888
#define SM_UP   0            // 5120 B
#define SM_BIAS 5120         // 1280 B
#define SM_DN   6400         // 128 px * 4 ranks * 4 B = 2048
#define SM_STG  9216
#define SMEM_SZ (SM_STG + 2 * STAGE_SZ)   // 84992

__device__ __forceinline__ void load_chunk(int q, uint32_t stg, int mtile, int nt, int b,
                                           int safe, int tid) {
    const int tap = q / 5, c0 = (q - tap * 5) * 64;
    const int ky = tap / 3, kx = tap - ky * 3;
    // A: 128 pixel rows x 64 fp16
    #pragma unroll 1
    for (int t = tid; t < 1024; t += NTH) {
        int row = t >> 3, sub = t & 7;
        int pi = row >> 6, cl = row & 63;
        int pp = (mtile * 2 + pi + ky) * PAD_HW + cl + kx;
        size_t off = ((size_t)b * PIX_PAD + pp) * CIN + c0 + sub * 8;
        uint32_t d = stg + A_OFF + (uint32_t)row * 128 + ((uint32_t)(sub ^ (row & 7)) << 4);
        CP16(d, g_X + off);
    }
    // B: 160 cout rows x 64 fp16
    #pragma unroll 1
    for (int t = tid; t < 1280; t += NTH) {
        int row = t >> 3, sub = t & 7;
        size_t off = (size_t)(nt * 160 + row) * KTOT + tap * CIN + c0 + sub * 8;
        uint32_t d = stg + B_OFF + (uint32_t)row * 128 + ((uint32_t)(sub ^ (row & 7)) << 4);
        CP16(d, g_W + off);
    }
    // B-down: 8 rank rows x 64 fp16 (rows 4..7 zero)
    if (tid < 64) {
        int row = tid >> 3, sub = tid & 7;
        size_t off = ((size_t)safe * 8 + row) * KTOT + tap * CIN + c0 + sub * 8;
        uint32_t d = stg + BD_OFF + (uint32_t)row * 128 + ((uint32_t)(sub ^ row) << 4);
        CP16(d, g_D + off);
    }
}

__global__ __launch_bounds__(NTH)
void gemm_kernel(const float* __restrict__ conv_b, const float* __restrict__ up_w,
                 const int* __restrict__ lora_id, float* __restrict__ out) {
    extern __shared__ __align__(1024) char sm[];
    const uint32_t smb = smem_u32(sm);
    const int tid = threadIdx.x, wid = tid >> 5, lid = tid & 31;
    const int wm = wid & 3, wn = wid >> 2;
    const int mtile = blockIdx.x;
    const int nt    = blockIdx.y;
    const int b     = blockIdx.z;

    const int idx = lora_id[b] / 4;
    const float sact = (idx >= 0) ? 1.f : 0.f;
    int safe = idx; if (safe < 0) safe = 0; if (safe > NLORA - 1) safe = NLORA - 1;

    float* up_s   = (float*)(sm + SM_UP);
    float* bias_s = (float*)(sm + SM_BIAS);
    float* dn_s   = (float*)(sm + SM_DN);
    for (int i = tid; i < COUT * RANK; i += NTH) up_s[i] = up_w[(size_t)safe * COUT * RANK + i];
    for (int i = tid; i < COUT; i += NTH) bias_s[i] = conv_b[i];

    float c[2][10][4];
    #pragma unroll
    for (int i = 0; i < 2; i++)
        #pragma unroll
        for (int j = 0; j < 10; j++)
            #pragma unroll
            for (int k = 0; k < 4; k++) c[i][j][k] = 0.f;
    float cdn[2][4];
    #pragma unroll
    for (int i = 0; i < 2; i++)
        #pragma unroll
        for (int k = 0; k < 4; k++) cdn[i][k] = 0.f;

    const int la7 = lid & 7, mq = lid >> 3;
    const uint32_t arow0 = (uint32_t)(wm * 32 + ((mq & 1) << 3) + la7) * 128;
    const uint32_t arow1 = arow0 + 16 * 128;
    const uint32_t acb = (uint32_t)(mq >> 1);
    uint32_t brow[5];
    #pragma unroll
    for (int jj = 0; jj < 5; jj++)
        brow[jj] = (uint32_t)(wn * 80 + jj * 16 + ((mq >> 1) << 3) + la7) * 128;
    const uint32_t bcb = (uint32_t)(mq & 1);
    const uint32_t bdrow = (uint32_t)la7 * 128;          // down tile: n-row = la7
    const uint32_t bdcb  = (uint32_t)(mq & 1);           // lanes 0-15 feed ldsm.x2

    load_chunk(0, smb + SM_STG, mtile, nt, b, safe, tid);
    CPCOMMIT();

    #pragma unroll 1
    for (int q = 0; q < 45; q++) {
        const uint32_t stg = smb + SM_STG + (uint32_t)(q & 1) * STAGE_SZ;
        if (q + 1 < 45) {
            load_chunk(q + 1, smb + SM_STG + (uint32_t)((q + 1) & 1) * STAGE_SZ, mtile, nt, b, safe, tid);
            CPCOMMIT();
            CPWAIT1();
        } else {
            CPWAIT0();
        }
        __syncthreads();

        const uint32_t aB = stg + A_OFF, bB = stg + B_OFF, dB = stg + BD_OFF;
        #pragma unroll
        for (int kk = 0; kk < 4; kk++) {
            const uint32_t ca = ((uint32_t)((kk * 2 + acb) ^ la7)) << 4;
            const uint32_t cb = ((uint32_t)((kk * 2 + bcb) ^ la7)) << 4;
            uint32_t a0[4], a1[4];
            ldsm4(a0[0], a0[1], a0[2], a0[3], aB + arow0 + ca);
            ldsm4(a1[0], a1[1], a1[2], a1[3], aB + arow1 + ca);
            uint32_t bf[10][2];
            #pragma unroll
            for (int jj = 0; jj < 5; jj++)
                ldsm4(bf[2 * jj][0], bf[2 * jj][1], bf[2 * jj + 1][0], bf[2 * jj + 1][1],
                      bB + brow[jj] + cb);
            #pragma unroll
            for (int j = 0; j < 10; j++) {
                mma_fp16(c[0][j][0], c[0][j][1], c[0][j][2], c[0][j][3],
                         a0[0], a0[1], a0[2], a0[3], bf[j][0], bf[j][1]);
                mma_fp16(c[1][j][0], c[1][j][1], c[1][j][2], c[1][j][3],
                         a1[0], a1[1], a1[2], a1[3], bf[j][0], bf[j][1]);
            }
            if (wn == 0) {   // block-uniform per warp: down-conv MMAs (N=8 rank tile)
                uint32_t bd0, bd1;
                ldsm2(bd0, bd1, dB + bdrow + (((uint32_t)((kk * 2 + bdcb) ^ la7)) << 4));
                mma_fp16(cdn[0][0], cdn[0][1], cdn[0][2], cdn[0][3],
                         a0[0], a0[1], a0[2], a0[3], bd0, bd1);
                mma_fp16(cdn[1][0], cdn[1][1], cdn[1][2], cdn[1][3],
                         a1[0], a1[1], a1[2], a1[3], bd0, bd1);
            }
        }
        __syncthreads();
    }

    // ---- share down results: wn0 warps own ranks in lanes (lid&3)<2 ----
    const int grp = lid >> 2, c2l = lid & 3;
    if (wn == 0) {
        #pragma unroll
        for (int i = 0; i < 2; i++)
            #pragma unroll
            for (int rr = 0; rr < 2; rr++) {
                const int rloc = wm * 32 + i * 16 + rr * 8 + grp;
                if (c2l == 0) {
                    dn_s[rloc * 4 + 0] = cdn[i][rr * 2 + 0];
                    dn_s[rloc * 4 + 1] = cdn[i][rr * 2 + 1];
                } else if (c2l == 1) {
                    dn_s[rloc * 4 + 2] = cdn[i][rr * 2 + 0];
                    dn_s[rloc * 4 + 3] = cdn[i][rr * 2 + 1];
                }
            }
    }
    __syncthreads();

    // ---- epilogue: out = acc + bias + sact * up . down ----
    const int c2 = c2l * 2;
    #pragma unroll
    for (int i = 0; i < 2; i++) {
        #pragma unroll
        for (int rr = 0; rr < 2; rr++) {
            const int rloc = wm * 32 + i * 16 + rr * 8 + grp;
            const int pixel = mtile * 128 + rloc;
            float4 dv = *(const float4*)&dn_s[rloc * 4];
            dv.x *= sact; dv.y *= sact; dv.z *= sact; dv.w *= sact;
            #pragma unroll
            for (int j = 0; j < 10; j++) {
                const int ng = nt * 160 + wn * 80 + j * 8 + c2;
                const float4 u0 = *(const float4*)&up_s[ng * 4];
                const float4 u1 = *(const float4*)&up_s[(ng + 1) * 4];
                const float add0 = bias_s[ng]     + u0.x * dv.x + u0.y * dv.y + u0.z * dv.z + u0.w * dv.w;
                const float add1 = bias_s[ng + 1] + u1.x * dv.x + u1.y * dv.y + u1.z * dv.z + u1.w * dv.w;
                out[((size_t)(b * COUT + ng))     * 4096 + pixel] = c[i][j][rr * 2 + 0] + add0;
                out[((size_t)(b * COUT + ng + 1)) * 4096 + pixel] = c[i][j][rr * 2 + 1] + add1;
            }
        }
    }
}

// ---------------- launch ----------------
extern "C" void kernel_launch(void* const* d_in, const int* in_sizes, int n_in,
                              void* d_out, int out_size)
{
    const float* x       = (const float*)d_in[0];
    const float* conv_w  = (const float*)d_in[1];
    const float* conv_b  = (const float*)d_in[2];
    const float* down_w  = (const float*)d_in[3];
    const float* up_w    = (const float*)d_in[4];
    const int*   lora_id = (const int*)d_in[5];
    float* out = (float*)d_out;

    cudaFuncSetAttribute(gemm_kernel, cudaFuncAttributeMaxDynamicSharedMemorySize, SMEM_SZ);

    convx_kernel<<<dim3(H_, 5, B_), 256>>>(x);
    border_kernel<<<256, 256>>>();
    convw_kernel<<<900, 256>>>(conv_w, down_w);
    gemm_kernel<<<dim3(32, 2, B_), NTH, SMEM_SZ>>>(conv_b, up_w, lora_id, out);
}

// round 9
// speedup vs baseline: 14.4151x; 1.2048x over previous
#include <cuda_runtime.h>
#include <cuda_fp16.h>
#include <cstdint>

// ---------------- problem constants ----------------
#define B_      16
#define CIN     320
#define COUT    320
#define H_      64
#define W_      64
#define RANK    4
#define NLORA   50
#define KTOT    2880
#define PAD_HW  66
#define PIX_PAD (PAD_HW * PAD_HW)

// ---------------- scratch ----------------
__device__ __align__(256) __half g_X[(size_t)B_ * PIX_PAD * CIN];
__device__ __align__(256) __half g_W[(size_t)COUT * KTOT];
__device__ __align__(256) __half g_D[(size_t)NLORA * 8 * KTOT];

// ---------------- PTX helpers ----------------
__device__ __forceinline__ uint32_t smem_u32(const void* p) {
    uint32_t a;
    asm("{ .reg .u64 t; cvta.to.shared.u64 t, %1; cvt.u32.u64 %0, t; }" : "=r"(a) : "l"(p));
    return a;
}
#define CP16(dst, src) asm volatile("cp.async.cg.shared.global [%0], [%1], 16;" :: "r"(dst), "l"(src))
#define CPCOMMIT()     asm volatile("cp.async.commit_group;" ::: "memory")
#define CPWAIT0()      asm volatile("cp.async.wait_group 0;" ::: "memory")

__device__ __forceinline__ void ldsm4(uint32_t& r0, uint32_t& r1, uint32_t& r2, uint32_t& r3, uint32_t a) {
    asm volatile("ldmatrix.sync.aligned.m8n8.x4.shared.b16 {%0,%1,%2,%3},[%4];"
                 : "=r"(r0), "=r"(r1), "=r"(r2), "=r"(r3) : "r"(a));
}
__device__ __forceinline__ void ldsm2(uint32_t& r0, uint32_t& r1, uint32_t a) {
    asm volatile("ldmatrix.sync.aligned.m8n8.x2.shared.b16 {%0,%1},[%2];"
                 : "=r"(r0), "=r"(r1) : "r"(a));
}
__device__ __forceinline__ void mma_fp16(float& c0, float& c1, float& c2, float& c3,
                                         uint32_t a0, uint32_t a1, uint32_t a2, uint32_t a3,
                                         uint32_t b0, uint32_t b1) {
    asm volatile("mma.sync.aligned.m16n8k16.row.col.f32.f16.f16.f32 "
                 "{%0,%1,%2,%3},{%4,%5,%6,%7},{%8,%9},{%0,%1,%2,%3};"
                 : "+f"(c0), "+f"(c1), "+f"(c2), "+f"(c3)
                 : "r"(a0), "r"(a1), "r"(a2), "r"(a3), "r"(b0), "r"(b1));
}

// ---------------- convx: x[b,c,h,w] fp32 -> g_X[b, padpix, c] fp16 ----------------
__global__ __launch_bounds__(256)
void convx_kernel(const float* __restrict__ x) {
    __shared__ uint4 s4[64][16];
    const int h = blockIdx.x, cc = blockIdx.y, b = blockIdx.z;
    const int c0 = cc * 64, tid = threadIdx.x;
    {
        const int c = tid >> 2, g0 = (tid & 3) * 4;
        const float* src = x + (((size_t)(b * CIN + c0 + c)) << 12) + h * 64;
        #pragma unroll
        for (int i = 0; i < 4; i++) {
            int g = g0 + i;
            s4[c][g ^ (c & 15)] = *(const uint4*)(src + g * 4);
        }
    }
    __syncthreads();
    const int wl = tid & 31, cg = tid >> 5;
    #pragma unroll
    for (int it = 0; it < 2; it++) {
        const int w = wl + it * 32;
        uint32_t hv[4];
        #pragma unroll
        for (int j = 0; j < 8; j += 2) {
            const int ca = cg * 8 + j, cb = ca + 1;
            float va = ((const float*)&s4[ca][(w >> 2) ^ (ca & 15)])[w & 3];
            float vb = ((const float*)&s4[cb][(w >> 2) ^ (cb & 15)])[w & 3];
            __half ha = __float2half_rn(va);
            __half hb = __float2half_rn(vb);
            hv[j >> 1] = (uint32_t)*(uint16_t*)&ha | ((uint32_t)*(uint16_t*)&hb << 16);
        }
        size_t base = ((size_t)b * PIX_PAD + (size_t)(h + 1) * PAD_HW + (w + 1)) * CIN + c0 + cg * 8;
        *(uint4*)&g_X[base] = make_uint4(hv[0], hv[1], hv[2], hv[3]);
    }
}

__global__ void border_kernel() {
    const int total = B_ * 260 * CIN;
    const __half z = __float2half_rn(0.f);
    for (int i = blockIdx.x * blockDim.x + threadIdx.x; i < total; i += gridDim.x * blockDim.x) {
        int c = i % CIN, t = i / CIN;
        int bi = t % 260, b = t / 260;
        int pp;
        if (bi < 66)       pp = bi;
        else if (bi < 132) pp = 65 * PAD_HW + (bi - 66);
        else if (bi < 196) pp = (bi - 131) * PAD_HW;
        else               pp = (bi - 195) * PAD_HW + 65;
        g_X[((size_t)b * PIX_PAD + pp) * CIN + c] = z;
    }
}

__global__ void convw_kernel(const float* __restrict__ conv_w, const float* __restrict__ down_w) {
    const int NW = COUT * CIN;
    const int ND = NLORA * 8 * CIN;
    for (int i = blockIdx.x * blockDim.x + threadIdx.x; i < NW + ND; i += gridDim.x * blockDim.x) {
        if (i < NW) {
            int n = i / CIN, c = i - n * CIN;
            #pragma unroll
            for (int tap = 0; tap < 9; tap++) {
                float v = conv_w[((size_t)n * CIN + c) * 9 + tap];
                g_W[(size_t)n * KTOT + tap * CIN + c] = __float2half_rn(v);
            }
        } else {
            int j = i - NW;
            int c = j % CIN, t = j / CIN;
            int r = t % 8, l = t / 8;
            #pragma unroll
            for (int tap = 0; tap < 9; tap++) {
                float v = 0.f;
                if (r < RANK)
                    v = down_w[(((size_t)l * RANK + r) * CIN + c) * 9 + tap];
                g_D[((size_t)l * 8 + r) * KTOT + tap * CIN + c] = __float2half_rn(v);
            }
        }
    }
}

// ---------------- main GEMM: CTA M=64 x N=160(+8), 2 CTAs/SM ----------------
#define NTH 256
#define A_OFF  0
#define B_OFF  8192
#define BD_OFF 28672
#define STAGE_SZ 29696
#define SM_UP   0            // 5120
#define SM_BIAS 5120         // 1280
#define SM_DN   6400         // 4 x 64px x 4r x 4B = 4096
#define SM_STG  11264
#define SMEM_SZ (SM_STG + 2 * STAGE_SZ)   // 70656

__global__ __launch_bounds__(NTH, 2)
void gemm_kernel(const float* __restrict__ conv_b, const float* __restrict__ up_w,
                 const int* __restrict__ lora_id, float* __restrict__ out) {
    extern __shared__ __align__(1024) char sm[];
    const uint32_t smb = smem_u32(sm);
    const int tid = threadIdx.x, wid = tid >> 5, lid = tid & 31;
    const int wm = wid & 1, wn = wid >> 1;           // 2(M) x 4(N)
    const int mtile = blockIdx.x;                    // 0..63: image row h
    const int nt    = blockIdx.y;                    // 0..1
    const int b     = blockIdx.z;

    const int idx = lora_id[b] / 4;
    const float sact = (idx >= 0) ? 1.f : 0.f;
    int safe = idx; if (safe < 0) safe = 0; if (safe > NLORA - 1) safe = NLORA - 1;

    float* up_s   = (float*)(sm + SM_UP);
    float* bias_s = (float*)(sm + SM_BIAS);
    float* dn_s   = (float*)(sm + SM_DN);
    for (int i = tid; i < COUT * RANK; i += NTH) up_s[i] = up_w[(size_t)safe * COUT * RANK + i];
    for (int i = tid; i < COUT; i += NTH) bias_s[i] = conv_b[i];

    // ---- hoisted load pointers (tap=0, c0=0 base) ----
    const __half* srcA[2];
    uint32_t dstA[2];
    #pragma unroll
    for (int i = 0; i < 2; i++) {
        int t = tid + i * NTH;            // 0..511
        int row = t >> 3, sub = t & 7;    // row = w coord 0..63
        srcA[i] = g_X + ((size_t)b * PIX_PAD + mtile * PAD_HW + row) * CIN + sub * 8;
        dstA[i] = A_OFF + (uint32_t)row * 128 + ((uint32_t)(sub ^ (row & 7)) << 4);
    }
    const __half* srcB[5];
    uint32_t dstB[5];
    #pragma unroll
    for (int j = 0; j < 5; j++) {
        int t = tid + j * NTH;            // 0..1279
        int row = t >> 3, sub = t & 7;    // row = cout 0..159
        srcB[j] = g_W + (size_t)(nt * 160 + row) * KTOT + sub * 8;
        dstB[j] = B_OFF + (uint32_t)row * 128 + ((uint32_t)(sub ^ (row & 7)) << 4);
    }
    const __half* srcD = g_D;
    uint32_t dstD = 0;
    if (tid < 64) {
        int row = tid >> 3, sub = tid & 7;
        srcD = g_D + ((size_t)safe * 8 + row) * KTOT + sub * 8;
        dstD = BD_OFF + (uint32_t)row * 128 + ((uint32_t)(sub ^ row) << 4);
    }

    float c[2][5][4];
    #pragma unroll
    for (int i = 0; i < 2; i++)
        #pragma unroll
        for (int j = 0; j < 5; j++)
            #pragma unroll
            for (int k = 0; k < 4; k++) c[i][j][k] = 0.f;
    float cdn[2][4];
    #pragma unroll
    for (int i = 0; i < 2; i++)
        #pragma unroll
        for (int k = 0; k < 4; k++) cdn[i][k] = 0.f;

    const int la7 = lid & 7, mq = lid >> 3;
    const uint32_t arow0 = (uint32_t)(wm * 32 + ((mq & 1) << 3) + la7) * 128;
    const uint32_t arow1 = arow0 + 16 * 128;
    const uint32_t acb = (uint32_t)(mq >> 1);
    const uint32_t brow0 = (uint32_t)(wn * 40 + ((mq >> 1) << 3) + la7) * 128;
    const uint32_t brow1 = brow0 + 16 * 128;
    const uint32_t brow2 = (uint32_t)(wn * 40 + 32 + la7) * 128;   // x2 tile (lanes 0-15)
    const uint32_t bdrow = (uint32_t)la7 * 128;
    const uint32_t bcb = (uint32_t)(mq & 1);

    // prologue: load chunk 0 (tap=0, c0=0: deltas are 0)
    {
        const uint32_t stg = smb + SM_STG;
        #pragma unroll
        for (int i = 0; i < 2; i++) CP16(stg + dstA[i], srcA[i]);
        #pragma unroll
        for (int j = 0; j < 5; j++) CP16(stg + dstB[j], srcB[j]);
        if (tid < 64) CP16(stg + dstD, srcD);
        CPCOMMIT();
    }

    #pragma unroll 1
    for (int q = 0; q < 45; q++) {
        const uint32_t stg = smb + SM_STG + (uint32_t)(q & 1) * STAGE_SZ;
        CPWAIT0();
        __syncthreads();

        if (q + 1 < 45) {
            const int q1 = q + 1;
            const int tap = q1 / 5, c0 = (q1 - tap * 5) * 64;
            const int ky = tap / 3, kx = tap - ky * 3;
            const int dA = (ky * PAD_HW + kx) * CIN + c0;
            const int dBD = tap * CIN + c0;
            const uint32_t stgn = smb + SM_STG + (uint32_t)(q1 & 1) * STAGE_SZ;
            #pragma unroll
            for (int i = 0; i < 2; i++) CP16(stgn + dstA[i], srcA[i] + dA);
            #pragma unroll
            for (int j = 0; j < 5; j++) CP16(stgn + dstB[j], srcB[j] + dBD);
            if (tid < 64) CP16(stgn + dstD, srcD + dBD);
            CPCOMMIT();
        }

        const uint32_t aB = stg + A_OFF, bB = stg + B_OFF, dB = stg + BD_OFF;
        #pragma unroll
        for (int kk = 0; kk < 4; kk++) {
            const uint32_t ca = ((uint32_t)((kk * 2 + acb) ^ la7)) << 4;
            const uint32_t cb = ((uint32_t)((kk * 2 + bcb) ^ la7)) << 4;
            uint32_t a0[4], a1[4];
            ldsm4(a0[0], a0[1], a0[2], a0[3], aB + arow0 + ca);
            ldsm4(a1[0], a1[1], a1[2], a1[3], aB + arow1 + ca);
            uint32_t bf[5][2];
            ldsm4(bf[0][0], bf[0][1], bf[1][0], bf[1][1], bB + brow0 + cb);
            ldsm4(bf[2][0], bf[2][1], bf[3][0], bf[3][1], bB + brow1 + cb);
            ldsm2(bf[4][0], bf[4][1], bB + brow2 + cb);
            #pragma unroll
            for (int j = 0; j < 5; j++) {
                mma_fp16(c[0][j][0], c[0][j][1], c[0][j][2], c[0][j][3],
                         a0[0], a0[1], a0[2], a0[3], bf[j][0], bf[j][1]);
                mma_fp16(c[1][j][0], c[1][j][1], c[1][j][2], c[1][j][3],
                         a1[0], a1[1], a1[2], a1[3], bf[j][0], bf[j][1]);
            }
            if (wn == kk) {   // rank-tile mma, k-sliced across wn groups
                uint32_t bd0, bd1;
                ldsm2(bd0, bd1, dB + bdrow + cb);
                mma_fp16(cdn[0][0], cdn[0][1], cdn[0][2], cdn[0][3],
                         a0[0], a0[1], a0[2], a0[3], bd0, bd1);
                mma_fp16(cdn[1][0], cdn[1][1], cdn[1][2], cdn[1][3],
                         a1[0], a1[1], a1[2], a1[3], bd0, bd1);
            }
        }
    }

    // ---- down partial exchange: each wn buffer holds its k-slice ----
    const int grp = lid >> 2, c2l = lid & 3;
    {
        float* dnw = dn_s + wn * 256;
        #pragma unroll
        for (int i = 0; i < 2; i++)
            #pragma unroll
            for (int rr = 0; rr < 2; rr++) {
                const int rloc = wm * 32 + i * 16 + rr * 8 + grp;
                if (c2l == 0) {
                    dnw[rloc * 4 + 0] = cdn[i][rr * 2 + 0];
                    dnw[rloc * 4 + 1] = cdn[i][rr * 2 + 1];
                } else if (c2l == 1) {
                    dnw[rloc * 4 + 2] = cdn[i][rr * 2 + 0];
                    dnw[rloc * 4 + 3] = cdn[i][rr * 2 + 1];
                }
            }
    }
    __syncthreads();

    // ---- epilogue ----
    #pragma unroll
    for (int i = 0; i < 2; i++) {
        #pragma unroll
        for (int rr = 0; rr < 2; rr++) {
            const int rloc = wm * 32 + i * 16 + rr * 8 + grp;
            const int pixel = mtile * 64 + rloc;
            float4 dv = make_float4(0.f, 0.f, 0.f, 0.f);
            #pragma unroll
            for (int s = 0; s < 4; s++) {
                float4 t = *(const float4*)&dn_s[s * 256 + rloc * 4];
                dv.x += t.x; dv.y += t.y; dv.z += t.z; dv.w += t.w;
            }
            dv.x *= sact; dv.y *= sact; dv.z *= sact; dv.w *= sact;
            #pragma unroll
            for (int j = 0; j < 5; j++) {
                const int ng = nt * 160 + wn * 40 + j * 8 + c2l * 2;
                const float4 u0 = *(const float4*)&up_s[ng * 4];
                const float4 u1 = *(const float4*)&up_s[(ng + 1) * 4];
                const float add0 = bias_s[ng]     + u0.x * dv.x + u0.y * dv.y + u0.z * dv.z + u0.w * dv.w;
                const float add1 = bias_s[ng + 1] + u1.x * dv.x + u1.y * dv.y + u1.z * dv.z + u1.w * dv.w;
                out[((size_t)(b * COUT + ng))     * 4096 + pixel] = c[i][j][rr * 2 + 0] + add0;
                out[((size_t)(b * COUT + ng + 1)) * 4096 + pixel] = c[i][j][rr * 2 + 1] + add1;
            }
        }
    }
}

// ---------------- launch ----------------
extern "C" void kernel_launch(void* const* d_in, const int* in_sizes, int n_in,
                              void* d_out, int out_size)
{
    const float* x       = (const float*)d_in[0];
    const float* conv_w  = (const float*)d_in[1];
    const float* conv_b  = (const float*)d_in[2];
    const float* down_w  = (const float*)d_in[3];
    const float* up_w    = (const float*)d_in[4];
    const int*   lora_id = (const int*)d_in[5];
    float* out = (float*)d_out;

    cudaFuncSetAttribute(gemm_kernel, cudaFuncAttributeMaxDynamicSharedMemorySize, SMEM_SZ);

    convx_kernel<<<dim3(H_, 5, B_), 256>>>(x);
    border_kernel<<<256, 256>>>();
    convw_kernel<<<900, 256>>>(conv_w, down_w);
    gemm_kernel<<<dim3(64, 2, B_), NTH, SMEM_SZ>>>(conv_b, up_w, lora_id, out);
}